// round 4
// baseline (speedup 1.0000x reference)
#include <cuda_runtime.h>
#include <cstdint>

#define HG_L 16
#define HG_T (1u << 19)
#define HG_TMASK (HG_T - 1u)
#define WIDTH 64

#define P1 2654435761u
#define P2 805459861u
#define P3 3674653429u

typedef unsigned long long u64;

// floor(16 * 1.5^l) for l = 0..15
__constant__ float c_res[HG_L] = {
    16.f, 24.f, 36.f, 54.f, 81.f, 121.f, 182.f, 273.f,
    410.f, 615.f, 922.f, 1383.f, 2075.f, 3113.f, 4670.f, 7006.f
};

// packed f32x2 fma (Blackwell FFMA2)
__device__ __forceinline__ u64 ffma2(u64 a, u64 b, u64 c) {
    u64 d;
    asm("fma.rn.f32x2 %0, %1, %2, %3;" : "=l"(d) : "l"(a), "l"(b), "l"(c));
    return d;
}
__device__ __forceinline__ u64 dup2(float x) {
    u64 d;
    asm("mov.b64 %0, {%1, %1};" : "=l"(d) : "f"(x));
    return d;
}

// Blackwell 256-bit read-only global load (sm_100+): 4 table entries at once.
__device__ __forceinline__ void ldg256(const float* p, float4& lo, float4& hi) {
    asm("ld.global.nc.v8.f32 {%0,%1,%2,%3,%4,%5,%6,%7}, [%8];"
        : "=f"(lo.x), "=f"(lo.y), "=f"(lo.z), "=f"(lo.w),
          "=f"(hi.x), "=f"(hi.y), "=f"(hi.z), "=f"(hi.w)
        : "l"(p));
}

// One x-corner pair: corners id0=(ax0^e)&M and id1=((ax0+1)^e)&M.
// When (ax0&3)!=3 both lie in the same aligned 4-entry group -> one 32B load.
// Otherwise a predicated extra float2 load fetches the partner. Branchless.
__device__ __forceinline__ void gather_pair(const float2* __restrict__ base,
                                            uint32_t ax0, uint32_t e,
                                            bool ingroup, uint32_t mask,
                                            float vx0, float vx1, float wt,
                                            float& f0, float& f1) {
    uint32_t id0 = (ax0 ^ e) & HG_TMASK;
    int i0 = id0 & 3;
    int i1 = i0 ^ (int)mask;

    float4 lo, hi;
    ldg256((const float*)(base + (id0 & ~3u)), lo, hi);

    float2 v = make_float2(0.f, 0.f);
    if (!ingroup) v = __ldg(base + (((ax0 + 1u) ^ e) & HG_TMASK));

    float4 h0 = (i0 & 2) ? hi : lo;
    float4 h1v = (i1 & 2) ? hi : lo;
    float e0x = (i0 & 1) ? h0.z : h0.x;
    float e0y = (i0 & 1) ? h0.w : h0.y;
    float e1x = ingroup ? ((i1 & 1) ? h1v.z : h1v.x) : v.x;
    float e1y = ingroup ? ((i1 & 1) ? h1v.w : h1v.y) : v.y;

    f0 = fmaf(wt, fmaf(vx0, e0x, vx1 * e1x), f0);
    f1 = fmaf(wt, fmaf(vx0, e0y, vx1 * e1y), f1);
}

// Accumulate one level's (f0, f1) into h1 (32 packed f32x2) with W1 rows
// (row, row+1); warp-uniform broadcast LDS.128.
__device__ __forceinline__ void acc_l1(const float* __restrict__ W1s, int row,
                                       float f0, float f1, u64* __restrict__ hp) {
    u64 F0 = dup2(f0), F1 = dup2(f1);
    const ulonglong2* w0 = (const ulonglong2*)(W1s + row * WIDTH);
    const ulonglong2* w1 = (const ulonglong2*)(W1s + (row + 1) * WIDTH);
#pragma unroll
    for (int j = 0; j < 16; j++) {
        ulonglong2 a = w0[j];
        ulonglong2 b = w1[j];
        hp[2 * j + 0] = ffma2(F0, a.x, ffma2(F1, b.x, hp[2 * j + 0]));
        hp[2 * j + 1] = ffma2(F0, a.y, ffma2(F1, b.y, hp[2 * j + 1]));
    }
}

__device__ __forceinline__ void encode3(float x0, float x1, float x2,
                                        const float* __restrict__ tab,
                                        const float* __restrict__ W1s,
                                        int kbase, u64* __restrict__ hp) {
#pragma unroll 1
    for (int l = 0; l < HG_L; l++) {
        float r = c_res[l];
        float px = x0 * r, py = x1 * r, pz = x2 * r;
        float fx = floorf(px), fy = floorf(py), fz = floorf(pz);
        float wx = px - fx, wy = py - fy, wz = pz - fz;

        uint32_t ax0 = (uint32_t)fx;
        uint32_t ey[2], ez[2];
        ey[0] = (uint32_t)fy * P1;  ey[1] = ey[0] + P1;
        ez[0] = (uint32_t)fz * P2;  ez[1] = ez[0] + P2;
        float vx0 = 1.f - wx, vx1 = wx;
        float vy[2] = {1.f - wy, wy};
        float vz[2] = {1.f - wz, wz};

        const bool ingroup = (ax0 & 3u) != 3u;
        const uint32_t mask = (ax0 & 1u) ? 3u : 1u;
        const float2* base = (const float2*)tab + (size_t)l * HG_T;

        float f0 = 0.f, f1 = 0.f;
#pragma unroll
        for (int c = 0; c < 4; c++) {
            const int by = c >> 1, bz = c & 1;
            gather_pair(base, ax0, ey[by] ^ ez[bz], ingroup, mask,
                        vx0, vx1, vy[by] * vz[bz], f0, f1);
        }
        acc_l1(W1s, kbase + 2 * l, f0, f1, hp);
    }
}

__device__ __forceinline__ void encode4(float x0, float x1, float x2, float x3,
                                        const float* __restrict__ tab,
                                        const float* __restrict__ W1s,
                                        int kbase, u64* __restrict__ hp) {
#pragma unroll 1
    for (int l = 0; l < HG_L; l++) {
        float r = c_res[l];
        float px = x0 * r, py = x1 * r, pz = x2 * r, pw = x3 * r;
        float fx = floorf(px), fy = floorf(py), fz = floorf(pz), fw = floorf(pw);
        float wx = px - fx, wy = py - fy, wz = pz - fz, ww = pw - fw;

        uint32_t ax0 = (uint32_t)fx;
        uint32_t ey[2], ez[2], ew[2];
        ey[0] = (uint32_t)fy * P1;  ey[1] = ey[0] + P1;
        ez[0] = (uint32_t)fz * P2;  ez[1] = ez[0] + P2;
        ew[0] = (uint32_t)fw * P3;  ew[1] = ew[0] + P3;
        float vx0 = 1.f - wx, vx1 = wx;
        float vy[2] = {1.f - wy, wy};
        float vz[2] = {1.f - wz, wz};
        float vw[2] = {1.f - ww, ww};

        const bool ingroup = (ax0 & 3u) != 3u;
        const uint32_t mask = (ax0 & 1u) ? 3u : 1u;
        const float2* base = (const float2*)tab + (size_t)l * HG_T;

        float f0 = 0.f, f1 = 0.f;
#pragma unroll
        for (int c = 0; c < 8; c++) {
            const int by = (c >> 2) & 1, bz = (c >> 1) & 1, bw = c & 1;
            gather_pair(base, ax0, ey[by] ^ ez[bz] ^ ew[bw], ingroup, mask,
                        vx0, vx1, vy[by] * (vz[bz] * vw[bw]), f0, f1);
        }
        acc_l1(W1s, kbase + 2 * l, f0, f1, hp);
    }
}

__global__ __launch_bounds__(256, 2)
void hashgrid_mlp_kernel(const float* __restrict__ fc,
                         const float* __restrict__ fn,
                         const float* __restrict__ pe,
                         const float* __restrict__ pos_tab,
                         const float* __restrict__ nrm_tab,
                         const float* __restrict__ pose_tab,
                         const float* __restrict__ W1,
                         const float* __restrict__ W2,
                         const float* __restrict__ W3,
                         float* __restrict__ out, int n) {
    __shared__ float W1s[96 * WIDTH];       // 24 KB
    __shared__ float W2Ts[WIDTH * WIDTH];   // 16 KB (transposed)
    __shared__ float W3s[WIDTH * 9];        // 2.25 KB

    const int tid = threadIdx.x;
    for (int i = tid; i < 96 * WIDTH; i += 256) W1s[i] = W1[i];
    for (int i = tid; i < WIDTH * WIDTH; i += 256) {
        int k = i >> 6, j = i & 63;
        W2Ts[j * WIDTH + k] = W2[i];
    }
    for (int i = tid; i < WIDTH * 9; i += 256) W3s[i] = W3[i];
    __syncthreads();

    const int idx = blockIdx.x * 256 + tid;
    if (idx >= n) return;

    u64 hp[32];
#pragma unroll
    for (int j = 0; j < 32; j++) hp[j] = 0ull;

    {
        float x0 = __ldg(fc + (size_t)idx * 3 + 0);
        float x1 = __ldg(fc + (size_t)idx * 3 + 1);
        float x2 = __ldg(fc + (size_t)idx * 3 + 2);
        encode3(x0, x1, x2, pos_tab, W1s, 0, hp);
    }
    {
        float x0 = __ldg(fn + (size_t)idx * 3 + 0);
        float x1 = __ldg(fn + (size_t)idx * 3 + 1);
        float x2 = __ldg(fn + (size_t)idx * 3 + 2);
        encode3(x0, x1, x2, nrm_tab, W1s, 32, hp);
    }
    {
        float x0 = __ldg(pe + (size_t)idx * 4 + 0);
        float x1 = __ldg(pe + (size_t)idx * 4 + 1);
        float x2 = __ldg(pe + (size_t)idx * 4 + 2);
        float x3 = __ldg(pe + (size_t)idx * 4 + 3);
        encode4(x0, x1, x2, x3, pose_tab, W1s, 64, hp);
    }

    // unpack + relu(layer 1)
    float h1[WIDTH];
#pragma unroll
    for (int j = 0; j < 32; j++) {
        float lo, hi;
        asm("mov.b64 {%0, %1}, %2;" : "=f"(lo), "=f"(hi) : "l"(hp[j]));
        h1[2 * j + 0] = fmaxf(lo, 0.f);
        h1[2 * j + 1] = fmaxf(hi, 0.f);
    }

    // layers 2 + 3 streamed
    float acc[9];
#pragma unroll
    for (int o = 0; o < 9; o++) acc[o] = 0.f;

#pragma unroll 1
    for (int j = 0; j < WIDTH; j++) {
        const float* wr = W2Ts + j * WIDTH;
        float s0 = 0.f, s1 = 0.f, s2 = 0.f, s3 = 0.f;
#pragma unroll
        for (int k = 0; k < WIDTH; k += 4) {
            float4 a = *(const float4*)(wr + k);
            s0 = fmaf(h1[k + 0], a.x, s0);
            s1 = fmaf(h1[k + 1], a.y, s1);
            s2 = fmaf(h1[k + 2], a.z, s2);
            s3 = fmaf(h1[k + 3], a.w, s3);
        }
        float s = fmaxf((s0 + s1) + (s2 + s3), 0.f);
        const float* w3 = W3s + j * 9;
#pragma unroll
        for (int o = 0; o < 9; o++) acc[o] = fmaf(s, w3[o], acc[o]);
    }

    float* op = out + (size_t)idx * 9;
#pragma unroll
    for (int o = 0; o < 9; o++) op[o] = acc[o];
}

extern "C" void kernel_launch(void* const* d_in, const int* in_sizes, int n_in,
                              void* d_out, int out_size) {
    const float* fc = (const float*)d_in[0];
    const float* fn = (const float*)d_in[1];
    const float* pe = (const float*)d_in[2];
    const float* pt = (const float*)d_in[3];
    const float* nt = (const float*)d_in[4];
    const float* qt = (const float*)d_in[5];
    const float* W1 = (const float*)d_in[6];
    const float* W2 = (const float*)d_in[7];
    const float* W3 = (const float*)d_in[8];
    float* out = (float*)d_out;

    const int n = in_sizes[0] / 3;
    const int blocks = (n + 255) / 256;
    hashgrid_mlp_kernel<<<blocks, 256>>>(fc, fn, pe, pt, nt, qt, W1, W2, W3, out, n);
}